// round 9
// baseline (speedup 1.0000x reference)
#include <cuda_runtime.h>
#include <cuda_bf16.h>
#include <cstdint>

#define B 8192
#define D 128
#define KD 128
#define AST 136           // smem row stride in bf16 (272B, conflict-free ldmatrix)
#define NOFF 33           // col partial slots (offsets 0..32)
#define TPB 256
#define FEPS 1e-5f

// ---------------- device scratch ----------------
__device__ float  g_sq[B];
__device__ float2 g_sl[B];            // (sq_j, label bits)
__device__ uint2  g_hi[B * 32];       // bf16 rows ([B][D] bf16 = 2MB)
__device__ float  g_rm1[2 * B];
__device__ float  g_rm2[2 * B];
__device__ float  g_rmn[2 * B];
__device__ float  g_cm1[NOFF * B];
__device__ float  g_cm2[NOFF * B];
__device__ float  g_cmn[NOFF * B];
__device__ float  g_bsum[64];

// smem byte offsets
#define SM_A   0
#define SM_B0  34816
#define SM_B1  69632
#define SM_ST  104448                  // staging: col flush [2][3][128]f / row final [4][3][128]f
#define SMEM_TOTAL 110592

__device__ __forceinline__ uint32_t s2u(const void* p) {
    uint32_t a;
    asm("{ .reg .u64 t; cvta.to.shared.u64 t, %1; cvt.u32.u64 %0, t; }" : "=r"(a) : "l"(p));
    return a;
}
__device__ __forceinline__ void cpa16(uint32_t dst, const void* src) {
    asm volatile("cp.async.cg.shared.global [%0], [%1], 16;" :: "r"(dst), "l"(src));
}
#define CP_COMMIT() asm volatile("cp.async.commit_group;" ::: "memory")
#define CP_WAIT0()  asm volatile("cp.async.wait_group 0;" ::: "memory")

__device__ __forceinline__ void ldsm4(uint32_t& r0, uint32_t& r1, uint32_t& r2,
                                      uint32_t& r3, uint32_t a) {
    asm volatile("ldmatrix.sync.aligned.m8n8.x4.shared.b16 {%0,%1,%2,%3}, [%4];"
                 : "=r"(r0), "=r"(r1), "=r"(r2), "=r"(r3) : "r"(a));
}
__device__ __forceinline__ void mma16816(float* c, const uint32_t* a, const uint32_t* b) {
    asm volatile(
        "mma.sync.aligned.m16n8k16.row.col.f32.bf16.bf16.f32 "
        "{%0,%1,%2,%3}, {%4,%5,%6,%7}, {%8,%9}, {%0,%1,%2,%3};"
        : "+f"(c[0]), "+f"(c[1]), "+f"(c[2]), "+f"(c[3])
        : "r"(a[0]), "r"(a[1]), "r"(a[2]), "r"(a[3]), "r"(b[0]), "r"(b[1]));
}

// top-2-min merge helper
__device__ __forceinline__ void t2(float& a1, float& a2, float b1, float b2) {
    a2 = fminf(fminf(a2, b2), fmaxf(a1, b1));
    a1 = fminf(a1, b1);
}

// ---------------- prepass: bf16 convert + row norms + (sq,label) ----------------
__global__ void prep_kernel(const float* __restrict__ F, const int* __restrict__ lab) {
    int gtid = blockIdx.x * blockDim.x + threadIdx.x;
    int row  = gtid >> 5, lane = gtid & 31;
    float4 v = reinterpret_cast<const float4*>(F)[row * 32 + lane];
    unsigned short h[4];
    h[0] = __bfloat16_as_ushort(__float2bfloat16(v.x));
    h[1] = __bfloat16_as_ushort(__float2bfloat16(v.y));
    h[2] = __bfloat16_as_ushort(__float2bfloat16(v.z));
    h[3] = __bfloat16_as_ushort(__float2bfloat16(v.w));
    g_hi[row * 32 + lane] = make_uint2((uint32_t)h[0] | ((uint32_t)h[1] << 16),
                                       (uint32_t)h[2] | ((uint32_t)h[3] << 16));
    float s = v.x * v.x + v.y * v.y + v.z * v.z + v.w * v.w;
    #pragma unroll
    for (int d = 16; d > 0; d >>= 1) s += __shfl_xor_sync(0xffffffffu, s, d);
    if (lane == 0) {
        g_sq[row] = s;
        g_sl[row] = make_float2(s, __int_as_float(lab[row]));
    }
}

__device__ __forceinline__ void issue_tile(uint32_t smb, int dst_off, int r0, int tid) {
    const char* base = reinterpret_cast<const char*>(g_hi);
    #pragma unroll
    for (int p = 0; p < 8; p++) {
        int c   = p * TPB + tid;
        int row = c >> 4, off = c & 15;
        cpa16(smb + dst_off + row * (AST * 2) + off * 16,
              base + (r0 + row) * 256 + off * 16);
    }
}

// ---------------- symmetric HMMA + row/col hard-mining kernel ----------------
__global__ __launch_bounds__(TPB)
void hmma_kernel(const int* __restrict__ lab) {
    extern __shared__ char smem[];
    const uint32_t smb = s2u(smem);
    float* scm = reinterpret_cast<float*>(smem + SM_ST);
    const int tid = threadIdx.x;
    const int wid = tid >> 5, lane = tid & 31;
    const int wm  = wid >> 2, wn = wid & 3;      // warp grid 2x4, tile 64x32
    const int q   = lane >> 2, tq = lane & 3;
    const int it  = blockIdx.x, slot = blockIdx.y;
    const int i0  = it * 128;
    const float FINF = __int_as_float(0x7f800000);

    const int off_beg = slot ? 17 : 0;
    const int off_end = slot ? (it < 32 ? 33 : 32) : 17;

    // prologue: A tile + first B tile
    issue_tile(smb, SM_A, i0, tid);
    issue_tile(smb, SM_B0, (((it + off_beg) & 63) * 128), tid);
    CP_COMMIT();

    // ldmatrix addresses
    const int lrow = lane & 7, grp = lane >> 3;
    int arow[4];
    #pragma unroll
    for (int mt = 0; mt < 4; mt++)
        arow[mt] = (wm * 64 + mt * 16 + lrow + (grp & 1) * 8) * AST;
    const int acol = (grp >> 1) * 8;
    int bb[2];
    #pragma unroll
    for (int ntp = 0; ntp < 2; ntp++)
        bb[ntp] = (wn * 32 + ntp * 16 + ((grp >> 1) & 1) * 8 + lrow) * AST
                + (grp & 1) * 8;

    int   li8[8];
    float sqa[8];
    #pragma unroll
    for (int mt = 0; mt < 4; mt++)
        #pragma unroll
        for (int h = 0; h < 2; h++) {
            int i = i0 + wm * 64 + mt * 16 + q + 8 * h;
            li8[mt * 2 + h] = lab[i];
            sqa[mt * 2 + h] = g_sq[i];
        }

    float m1[8], m2[8], mn[8];
    #pragma unroll
    for (int r = 0; r < 8; r++) { m1[r] = FINF; m2[r] = FINF; mn[r] = FINF; }

    CP_WAIT0();
    __syncthreads();

    for (int t = 0; t < off_end - off_beg; t++) {
        const int off  = off_beg + t;
        const int jt   = (it + off) & 63;
        const int j0   = jt * 128;
        const int bufo = (t & 1) ? SM_B1 : SM_B0;
        const bool diag = (off == 0);

        if (off + 1 < off_end) {
            issue_tile(smb, (t & 1) ? SM_B0 : SM_B1, (((it + off + 1) & 63) * 128), tid);
            CP_COMMIT();
        }

        float acc[4][4][4];
        #pragma unroll
        for (int mt = 0; mt < 4; mt++)
            #pragma unroll
            for (int nt = 0; nt < 4; nt++)
                #pragma unroll
                for (int e = 0; e < 4; e++) acc[mt][nt][e] = 0.f;

        #pragma unroll
        for (int ks = 0; ks < KD / 16; ks++) {
            const int k0 = ks * 16;
            uint32_t a[4][4], b[4][2];
            #pragma unroll
            for (int mt = 0; mt < 4; mt++)
                ldsm4(a[mt][0], a[mt][1], a[mt][2], a[mt][3],
                      smb + SM_A + (arow[mt] + k0 + acol) * 2);
            ldsm4(b[0][0], b[0][1], b[1][0], b[1][1],
                  smb + bufo + (bb[0] + k0) * 2);
            ldsm4(b[2][0], b[2][1], b[3][0], b[3][1],
                  smb + bufo + (bb[1] + k0) * 2);
            #pragma unroll
            for (int mt = 0; mt < 4; mt++)
                #pragma unroll
                for (int nt = 0; nt < 4; nt++)
                    mma16816(acc[mt][nt], a[mt], b[nt]);
        }

        // ---- epilogue: row trackers (t=sqj-2dot) + col trackers (u=sqi-2dot) ----
        float cc1[8], cc2[8], ccn[8];
        #pragma unroll
        for (int ci = 0; ci < 8; ci++) { cc1[ci] = FINF; cc2[ci] = FINF; ccn[ci] = FINF; }

        #pragma unroll
        for (int nt = 0; nt < 4; nt++) {
            const int jl0 = wn * 32 + nt * 8 + 2 * tq, jl1 = jl0 + 1;
            float2 sl0 = g_sl[j0 + jl0], sl1 = g_sl[j0 + jl1];
            const int lj0 = __float_as_int(sl0.y), lj1 = __float_as_int(sl1.y);
            const int ci0 = nt * 2, ci1 = nt * 2 + 1;
            #pragma unroll
            for (int mt = 0; mt < 4; mt++)
                #pragma unroll
                for (int h = 0; h < 2; h++) {
                    const int r  = mt * 2 + h;
                    const int il = wm * 64 + mt * 16 + q + 8 * h;
                    const float dot0 = acc[mt][nt][2 * h], dot1 = acc[mt][nt][2 * h + 1];
                    const float t0 = fmaf(-2.f, dot0, sl0.x), t1 = fmaf(-2.f, dot1, sl1.x);
                    const float u0 = fmaf(-2.f, dot0, sqa[r]), u1 = fmaf(-2.f, dot1, sqa[r]);
                    const bool s0 = (li8[r] == lj0), s1 = (li8[r] == lj1);
                    const bool rk0 = !diag || (jl0 >= il), ck0 = !diag || (jl0 > il);
                    const bool rk1 = !diag || (jl1 >= il), ck1 = !diag || (jl1 > il);
                    t2(m1[r], m2[r], (s0 && rk0) ? t0 : FINF, FINF);
                    mn[r] = fminf(mn[r], (!s0 && rk0) ? t0 : FINF);
                    t2(m1[r], m2[r], (s1 && rk1) ? t1 : FINF, FINF);
                    mn[r] = fminf(mn[r], (!s1 && rk1) ? t1 : FINF);
                    t2(cc1[ci0], cc2[ci0], (s0 && ck0) ? u0 : FINF, FINF);
                    ccn[ci0] = fminf(ccn[ci0], (!s0 && ck0) ? u0 : FINF);
                    t2(cc1[ci1], cc2[ci1], (s1 && ck1) ? u1 : FINF, FINF);
                    ccn[ci1] = fminf(ccn[ci1], (!s1 && ck1) ? u1 : FINF);
                }
        }

        // col reduce across q (lanes xor 4,8,16), then across wm via smem
        #pragma unroll
        for (int d = 4; d < 32; d <<= 1) {
            #pragma unroll
            for (int ci = 0; ci < 8; ci++) {
                float o1 = __shfl_xor_sync(0xffffffffu, cc1[ci], d);
                float o2 = __shfl_xor_sync(0xffffffffu, cc2[ci], d);
                float on = __shfl_xor_sync(0xffffffffu, ccn[ci], d);
                t2(cc1[ci], cc2[ci], o1, o2);
                ccn[ci] = fminf(ccn[ci], on);
            }
        }
        if (q == 0) {
            #pragma unroll
            for (int nt = 0; nt < 4; nt++)
                #pragma unroll
                for (int p = 0; p < 2; p++) {
                    int col = wn * 32 + nt * 8 + 2 * tq + p, ci = nt * 2 + p;
                    scm[wm * 384 + 0 * 128 + col] = cc1[ci];
                    scm[wm * 384 + 1 * 128 + col] = cc2[ci];
                    scm[wm * 384 + 2 * 128 + col] = ccn[ci];
                }
        }
        __syncthreads();
        if (tid < 128) {
            float b1a = scm[tid],       b1b = scm[384 + tid];
            float b2a = scm[128 + tid], b2b = scm[384 + 128 + tid];
            float bna = scm[256 + tid], bnb = scm[384 + 256 + tid];
            float a1 = b1a, a2 = b2a;
            t2(a1, a2, b1b, b2b);
            g_cm1[off * B + j0 + tid] = a1;
            g_cm2[off * B + j0 + tid] = a2;
            g_cmn[off * B + j0 + tid] = fminf(bna, bnb);
        }

        if (off + 1 < off_end) CP_WAIT0();
        __syncthreads();
    }

    // FINF fill for missing off=32 col slots (pairs handled by it<32 CTAs)
    if (slot == 1 && it >= 32 && tid < 128) {
        int j0f = (it - 32) * 128 + tid;
        g_cm1[32 * B + j0f] = FINF;
        g_cm2[32 * B + j0f] = FINF;
        g_cmn[32 * B + j0f] = FINF;
    }

    // row reduce: quad (xor over tq bits), then across wn via smem
    #pragma unroll
    for (int d = 1; d < 4; d <<= 1) {
        #pragma unroll
        for (int r = 0; r < 8; r++) {
            float o1 = __shfl_xor_sync(0xffffffffu, m1[r], d);
            float o2 = __shfl_xor_sync(0xffffffffu, m2[r], d);
            float on = __shfl_xor_sync(0xffffffffu, mn[r], d);
            t2(m1[r], m2[r], o1, o2);
            mn[r] = fminf(mn[r], on);
        }
    }
    float* st = scm;   // reuse staging: [4][3][128]
    if (tq == 0) {
        #pragma unroll
        for (int mt = 0; mt < 4; mt++)
            #pragma unroll
            for (int h = 0; h < 2; h++) {
                int r = wm * 64 + mt * 16 + q + 8 * h;
                st[wn * 384 + 0 * 128 + r] = m1[mt * 2 + h];
                st[wn * 384 + 1 * 128 + r] = m2[mt * 2 + h];
                st[wn * 384 + 2 * 128 + r] = mn[mt * 2 + h];
            }
    }
    __syncthreads();
    if (tid < 128) {
        float a1 = FINF, a2 = FINF, an = FINF;
        #pragma unroll
        for (int w = 0; w < 4; w++) {
            float b1 = st[w * 384 + tid], b2 = st[w * 384 + 128 + tid],
                  bn = st[w * 384 + 256 + tid];
            t2(a1, a2, b1, b2);
            an = fminf(an, bn);
        }
        g_rm1[slot * B + i0 + tid] = a1;
        g_rm2[slot * B + i0 + tid] = a2;
        g_rmn[slot * B + i0 + tid] = an;
    }
}

// ---------------- merge partials + hinge + block sums ----------------
__global__ void merge1_kernel() {
    const int tid = threadIdx.x;
    const int row = blockIdx.x * 128 + tid;
    const float FINF = __int_as_float(0x7f800000);
    __shared__ float red[128];
    float a1 = FINF, a2 = FINF, an = FINF;
    #pragma unroll
    for (int s = 0; s < 2; s++) {
        t2(a1, a2, g_rm1[s * B + row], g_rm2[s * B + row]);
        an = fminf(an, g_rmn[s * B + row]);
    }
    #pragma unroll 4
    for (int s = 0; s < NOFF; s++) {
        t2(a1, a2, g_cm1[s * B + row], g_cm2[s * B + row]);
        an = fminf(an, g_cmn[s * B + row]);
    }
    float sqi = g_sq[row];
    float pos = sqrtf(fmaxf(sqi + a2 + FEPS, 0.f));
    float neg = sqrtf(fmaxf(sqi + an + FEPS, 0.f));
    red[tid] = fmaxf(1.0f + pos - neg, 0.f);
    __syncthreads();
    for (int s = 64; s > 0; s >>= 1) {
        if (tid < s) red[tid] += red[tid + s];
        __syncthreads();
    }
    if (tid == 0) g_bsum[blockIdx.x] = red[0];
}

__global__ void merge2_kernel(float* __restrict__ out) {
    int tid = threadIdx.x;   // 32
    float s = g_bsum[tid] + g_bsum[tid + 32];
    #pragma unroll
    for (int d = 16; d > 0; d >>= 1) s += __shfl_xor_sync(0xffffffffu, s, d);
    if (tid == 0) out[0] = s * (1.0f / (float)B);
}

extern "C" void kernel_launch(void* const* d_in, const int* in_sizes, int n_in,
                              void* d_out, int out_size) {
    (void)in_sizes; (void)n_in; (void)out_size;
    const float* F   = (const float*)d_in[0];
    const int*   lab = (const int*)d_in[1];
    float*       out = (float*)d_out;

    cudaFuncSetAttribute(hmma_kernel,
                         cudaFuncAttributeMaxDynamicSharedMemorySize, SMEM_TOTAL);

    prep_kernel<<<B / 8, TPB>>>(F, lab);
    dim3 grid(64, 2);
    hmma_kernel<<<grid, TPB, SMEM_TOTAL>>>(lab);
    merge1_kernel<<<64, 128>>>();
    merge2_kernel<<<1, 32>>>(out);
}